// round 1
// baseline (speedup 1.0000x reference)
#include <cuda_runtime.h>
#include <math.h>

#define BDIM 4
#define NDIM 4096
#define CDIM 1024
#define HDIM 16
#define DDIM 64
#define MDIM (BDIM*NDIM)     // 16384
#define NSPLIT 4

// Scratch (alloc-free: device globals)
__device__ float g_q[BDIM*HDIM*NDIM*DDIM];      // 64 MB, [B,H,N,D], elu+1 applied
__device__ float g_k[BDIM*HDIM*NDIM*DDIM];      // 64 MB
__device__ float g_v[BDIM*HDIM*NDIM*DDIM];      // 64 MB
__device__ float g_kvp[NSPLIT][BDIM*HDIM][DDIM*DDIM];  // partial kv outer products
__device__ float g_ksp[NSPLIT][BDIM*HDIM][DDIM];       // partial k row-sums
__device__ float g_attn[(size_t)MDIM*CDIM];     // 67 MB, [B,N,H*D] row-major

// ---------------------------------------------------------------------------
// Tiled SGEMM: 128x128 tile, BK=16, 256 threads, 8x8 per thread.
// MODE 0: C = x @ W_qkv, epilogue routes columns to q/k/v with elu+1 on q,k.
// MODE 1: C = g_attn @ W_out + bias -> Cout.
// ---------------------------------------------------------------------------
template<int MODE>
__global__ __launch_bounds__(256, 2)
void sgemm_kernel(const float* __restrict__ A, const float* __restrict__ Bmat,
                  const float* __restrict__ bias, float* __restrict__ Cout,
                  int Kdim, int Ndim)
{
    __shared__ float As[16][128];   // transposed: As[k][m]
    __shared__ float Bs[16][128];   // Bs[k][n]

    const float* Ap = (MODE == 1) ? (const float*)g_attn : A;

    const int tid = threadIdx.x;
    const int tx = tid & 15;        // column group
    const int ty = tid >> 4;        // row group
    const int row0 = blockIdx.y * 128;
    const int col0 = blockIdx.x * 128;

    float acc[8][8];
    #pragma unroll
    for (int i = 0; i < 8; i++)
        #pragma unroll
        for (int j = 0; j < 8; j++) acc[i][j] = 0.f;

    for (int k0 = 0; k0 < Kdim; k0 += 16) {
        // Load A tile 128x16 (transposed into As)
        #pragma unroll
        for (int i = 0; i < 2; i++) {
            int idx = tid * 2 + i;               // 0..511
            int r   = idx >> 2;                  // 0..127
            int kc  = (idx & 3) * 4;             // 0,4,8,12
            float4 a = *(const float4*)(Ap + (size_t)(row0 + r) * Kdim + k0 + kc);
            As[kc + 0][r] = a.x;
            As[kc + 1][r] = a.y;
            As[kc + 2][r] = a.z;
            As[kc + 3][r] = a.w;
        }
        // Load B tile 16x128
        #pragma unroll
        for (int i = 0; i < 2; i++) {
            int idx = tid * 2 + i;               // 0..511
            int kr  = idx >> 5;                  // 0..15
            int nc  = (idx & 31) * 4;            // 0..124
            *(float4*)&Bs[kr][nc] =
                *(const float4*)(Bmat + (size_t)(k0 + kr) * Ndim + col0 + nc);
        }
        __syncthreads();

        #pragma unroll
        for (int kk = 0; kk < 16; kk++) {
            float4 a0 = *(const float4*)&As[kk][ty * 8];       // broadcast within warp half
            float4 a1 = *(const float4*)&As[kk][ty * 8 + 4];
            float4 b0 = *(const float4*)&Bs[kk][tx * 4];       // phase-conflict-free LDS.128
            float4 b1 = *(const float4*)&Bs[kk][64 + tx * 4];
            float ar[8] = {a0.x, a0.y, a0.z, a0.w, a1.x, a1.y, a1.z, a1.w};
            float br[8] = {b0.x, b0.y, b0.z, b0.w, b1.x, b1.y, b1.z, b1.w};
            #pragma unroll
            for (int i = 0; i < 8; i++)
                #pragma unroll
                for (int j = 0; j < 8; j++)
                    acc[i][j] = fmaf(ar[i], br[j], acc[i][j]);
        }
        __syncthreads();
    }

    // Epilogue
    #pragma unroll
    for (int i = 0; i < 8; i++) {
        int row = row0 + ty * 8 + i;
        #pragma unroll
        for (int j = 0; j < 8; j++) {
            int col = col0 + ((j < 4) ? (tx * 4 + j) : (64 + tx * 4 + (j - 4)));
            float v = acc[i][j];
            if (MODE == 0) {
                // col in [0,3072): split (3, H, D)
                int t = col >> 10;
                int h = (col >> 6) & (HDIM - 1);
                int d = col & (DDIM - 1);
                int b = row >> 12;                 // row / 4096
                int n = row & (NDIM - 1);
                size_t o = (((size_t)(b * HDIM + h)) * NDIM + n) * DDIM + d;
                if (t == 0)      g_q[o] = (v > 0.f) ? v + 1.f : expf(v);  // elu(v)+1
                else if (t == 1) g_k[o] = (v > 0.f) ? v + 1.f : expf(v);
                else             g_v[o] = v;
            } else {
                Cout[(size_t)row * Ndim + col] = v + bias[col];
            }
        }
    }
}

// ---------------------------------------------------------------------------
// Stage 2a: partial kv[d][e] = sum_n k[n,d]*v[n,e] and ksum[d] over an N-split.
// grid (64 bh, NSPLIT), 256 threads, each thread owns a 4x4 block of kv.
// ---------------------------------------------------------------------------
__global__ __launch_bounds__(256)
void kv_kernel()
{
    const int bh    = blockIdx.x;
    const int split = blockIdx.y;
    const float* Kp = g_k + (size_t)bh * NDIM * DDIM;
    const float* Vp = g_v + (size_t)bh * NDIM * DDIM;

    const int tid = threadIdx.x;
    const int tc = tid & 15, tr = tid >> 4;
    const int d0 = tr * 4, e0 = tc * 4;

    __shared__ float ks[32][64];
    __shared__ float vs[32][64];

    float acc[4][4];
    float ksum[4] = {0.f, 0.f, 0.f, 0.f};
    #pragma unroll
    for (int i = 0; i < 4; i++)
        #pragma unroll
        for (int j = 0; j < 4; j++) acc[i][j] = 0.f;

    const int nBeg = split * (NDIM / NSPLIT);
    const int nEnd = nBeg + (NDIM / NSPLIT);

    for (int nb = nBeg; nb < nEnd; nb += 32) {
        #pragma unroll
        for (int i = 0; i < 2; i++) {
            int idx = tid * 2 + i;             // 0..511
            int r = idx >> 4;                  // 0..31
            int c = (idx & 15) * 4;            // 0..60
            *(float4*)&ks[r][c] = *(const float4*)(Kp + (size_t)(nb + r) * DDIM + c);
            *(float4*)&vs[r][c] = *(const float4*)(Vp + (size_t)(nb + r) * DDIM + c);
        }
        __syncthreads();
        #pragma unroll 4
        for (int nn = 0; nn < 32; nn++) {
            float kr[4], vr[4];
            #pragma unroll
            for (int i = 0; i < 4; i++) kr[i] = ks[nn][d0 + i];
            #pragma unroll
            for (int j = 0; j < 4; j++) vr[j] = vs[nn][e0 + j];
            #pragma unroll
            for (int i = 0; i < 4; i++) {
                ksum[i] += kr[i];
                #pragma unroll
                for (int j = 0; j < 4; j++)
                    acc[i][j] = fmaf(kr[i], vr[j], acc[i][j]);
            }
        }
        __syncthreads();
    }

    #pragma unroll
    for (int i = 0; i < 4; i++)
        #pragma unroll
        for (int j = 0; j < 4; j++)
            g_kvp[split][bh][(d0 + i) * DDIM + (e0 + j)] = acc[i][j];
    if (tc == 0)
        #pragma unroll
        for (int i = 0; i < 4; i++)
            g_ksp[split][bh][d0 + i] = ksum[i];
}

// ---------------------------------------------------------------------------
// Stage 2b: out[n,e] = (q[n,:] @ kv[:,e]) / (q[n,:]·ksum + 1e-6)
// grid (64 bh, 64 token-blocks of 64), 256 threads, 4x4 outputs per thread.
// Writes [B,N,H,D] so the final GEMM is a plain row-major read.
// ---------------------------------------------------------------------------
__global__ __launch_bounds__(256)
void attn_out_kernel()
{
    const int bh   = blockIdx.x;
    const int nblk = blockIdx.y;
    const int b = bh >> 4, h = bh & 15;
    const int tid = threadIdx.x;
    const int tx = tid & 15, ty = tid >> 4;

    __shared__ float kvs[DDIM][DDIM];   // 16 KB
    __shared__ float kss[DDIM];
    __shared__ float qs[64][65];        // padded rows, scalar reads only

    // Sum partial kv / ksum
    for (int idx = tid; idx < DDIM * DDIM; idx += 256) {
        float s = 0.f;
        #pragma unroll
        for (int sp = 0; sp < NSPLIT; sp++) s += g_kvp[sp][bh][idx];
        kvs[idx >> 6][idx & 63] = s;
    }
    if (tid < DDIM) {
        float s = 0.f;
        #pragma unroll
        for (int sp = 0; sp < NSPLIT; sp++) s += g_ksp[sp][bh][tid];
        kss[tid] = s;
    }

    // Load 64x64 q tile
    const int n0 = nblk * 64;
    const float* Qp = g_q + ((size_t)bh * NDIM + n0) * DDIM;
    #pragma unroll
    for (int i = 0; i < 4; i++) {
        int f = i * 256 + tid;             // float4 index, 0..1023
        int r = f >> 4;                    // 0..63
        int c = (f & 15) * 4;              // 0..60
        float4 v = *(const float4*)(Qp + (size_t)r * DDIM + c);
        qs[r][c + 0] = v.x; qs[r][c + 1] = v.y;
        qs[r][c + 2] = v.z; qs[r][c + 3] = v.w;
    }
    __syncthreads();

    float acc[4][4];
    float nrm[4] = {0.f, 0.f, 0.f, 0.f};
    #pragma unroll
    for (int i = 0; i < 4; i++)
        #pragma unroll
        for (int j = 0; j < 4; j++) acc[i][j] = 0.f;

    #pragma unroll 8
    for (int d = 0; d < DDIM; d++) {
        float4 kvr = *(const float4*)&kvs[d][tx * 4];
        float kvj[4] = {kvr.x, kvr.y, kvr.z, kvr.w};
        float ksd = kss[d];
        #pragma unroll
        for (int i = 0; i < 4; i++) {
            float qv = qs[ty * 4 + i][d];
            nrm[i] = fmaf(qv, ksd, nrm[i]);
            #pragma unroll
            for (int j = 0; j < 4; j++)
                acc[i][j] = fmaf(qv, kvj[j], acc[i][j]);
        }
    }

    #pragma unroll
    for (int i = 0; i < 4; i++) {
        int n = n0 + ty * 4 + i;
        float inv = 1.f / (nrm[i] + 1e-6f);
        size_t base = (((size_t)b * NDIM + n) * HDIM + h) * DDIM;
        #pragma unroll
        for (int j = 0; j < 4; j++)
            g_attn[base + tx * 4 + j] = acc[i][j] * inv;
    }
}

// ---------------------------------------------------------------------------
extern "C" void kernel_launch(void* const* d_in, const int* in_sizes, int n_in,
                              void* d_out, int out_size)
{
    const float* x    = (const float*)d_in[0];
    const float* Wqkv = (const float*)d_in[1];
    const float* Wout = (const float*)d_in[2];
    const float* bout = (const float*)d_in[3];
    float* out = (float*)d_out;

    // 1) qkv = x @ W_qkv, fused elu+1 + [B,H,N,D] transpose
    sgemm_kernel<0><<<dim3(3 * CDIM / 128, MDIM / 128), 256>>>(
        x, Wqkv, nullptr, nullptr, CDIM, 3 * CDIM);

    // 2a) kv / ksum reduction, split over N
    kv_kernel<<<dim3(BDIM * HDIM, NSPLIT), 256>>>();

    // 2b) numerator + normalizer + divide -> g_attn [B,N,C]
    attn_out_kernel<<<dim3(BDIM * HDIM, NDIM / 64), 256>>>();

    // 3) out = g_attn @ W_out + b_out
    sgemm_kernel<1><<<dim3(CDIM / 128, MDIM / 128), 256>>>(
        nullptr, Wout, bout, out, CDIM, CDIM);
}

// round 13
// speedup vs baseline: 1.4362x; 1.4362x over previous
#include <cuda_runtime.h>
#include <cuda_bf16.h>
#include <mma.h>
#include <math.h>
#include <stdint.h>

using namespace nvcuda;

#define BDIM 4
#define NDIM 4096
#define CDIM 1024
#define HDIM 16
#define DDIM 64
#define MDIM (BDIM*NDIM)     // 16384
#define NSPLIT 4

// wmma GEMM tiling
#define TM 128
#define TN 128
#define KC 32                 // fp32 K elements per chunk
#define A_LDM 40              // bf16 elements per A smem row (80B, conflict-free ldsm)
#define B_LDM 136             // bf16 elements per B smem row (272B, conflict-free ldsm)
#define A_PART_B (TM * A_LDM * 2)          // 10240 B
#define B_PART_B (KC * B_LDM * 2)          // 8704 B
#define STAGE_B  (2*A_PART_B + 2*B_PART_B) // 37888 B (Ahi,Alo,Bhi,Blo)
#define DYN_SMEM (2*STAGE_B)               // 75776 B (also covers 64KB f32 epilogue tile)

// Scratch (alloc-free: device globals)
__device__ float g_q[BDIM*HDIM*NDIM*DDIM];
__device__ float g_k[BDIM*HDIM*NDIM*DDIM];
__device__ float g_v[BDIM*HDIM*NDIM*DDIM];
__device__ float g_kvp[NSPLIT][BDIM*HDIM][DDIM*DDIM];
__device__ float g_ksp[NSPLIT][BDIM*HDIM][DDIM];
__device__ float g_attn[(size_t)MDIM*CDIM];

__device__ __forceinline__ void f2bf_pair(float v, __nv_bfloat16& hi, __nv_bfloat16& lo) {
    hi = __float2bfloat16(v);
    lo = __float2bfloat16(v - __bfloat162float(hi));
}

// ---------------------------------------------------------------------------
// wmma bf16 3-split GEMM. MODE 0: qkv = x @ W_qkv, elu+1 + [B,H,N,D] scatter.
//                         MODE 1: out = g_attn @ W_out + bias.
// 256 threads = 8 warps in 4(M) x 2(N); each warp owns 32x64 via 2x4 wmma accs.
// ---------------------------------------------------------------------------
template<int MODE>
__global__ __launch_bounds__(256, 1)
void gemm_wmma(const float* __restrict__ A, const float* __restrict__ Bm,
               const float* __restrict__ bias, float* __restrict__ Cout,
               int Kd, int Nd)
{
    extern __shared__ char sm[];
    const float* Ap = (MODE == 1) ? (const float*)g_attn : A;

    const int tid  = threadIdx.x;
    const int wid  = tid >> 5;
    const int wm   = wid >> 1;          // 0..3  (32-row slab)
    const int wn   = wid & 1;           // 0..1  (64-col slab)
    const int row0 = blockIdx.y * TM;
    const int col0 = blockIdx.x * TN;

    wmma::fragment<wmma::accumulator, 16, 16, 16, float> acc[2][4];
    #pragma unroll
    for (int i = 0; i < 2; i++)
        #pragma unroll
        for (int j = 0; j < 4; j++) wmma::fill_fragment(acc[i][j], 0.f);

    // Per-chunk global loads held in registers (prefetch double buffer)
    float4 pa[4], pb[4];

    auto issue_loads = [&](int k0) {
        #pragma unroll
        for (int r = 0; r < 4; r++) {
            const int task = r * 256 + tid;      // A: 0..1023
            const int m    = task >> 3;          // 0..127
            const int kg   = task & 7;           // float4 group
            pa[r] = *(const float4*)(Ap + (size_t)(row0 + m) * Kd + k0 + kg * 4);
        }
        #pragma unroll
        for (int r = 0; r < 4; r++) {
            const int task = r * 256 + tid;      // B: 0..1023
            const int kr   = task >> 5;          // 0..31
            const int ng   = task & 31;
            pb[r] = *(const float4*)(Bm + (size_t)(k0 + kr) * Nd + col0 + ng * 4);
        }
    };

    auto store_stage = [&](int s) {
        __nv_bfloat16* Ahi = (__nv_bfloat16*)(sm + s * STAGE_B);
        __nv_bfloat16* Alo = (__nv_bfloat16*)(sm + s * STAGE_B + A_PART_B);
        __nv_bfloat16* Bhi = (__nv_bfloat16*)(sm + s * STAGE_B + 2 * A_PART_B);
        __nv_bfloat16* Blo = (__nv_bfloat16*)(sm + s * STAGE_B + 2 * A_PART_B + B_PART_B);
        #pragma unroll
        for (int r = 0; r < 4; r++) {
            const int task = r * 256 + tid;
            const int m    = task >> 3;
            const int kg   = task & 7;
            __nv_bfloat16 h[4], l[4];
            f2bf_pair(pa[r].x, h[0], l[0]); f2bf_pair(pa[r].y, h[1], l[1]);
            f2bf_pair(pa[r].z, h[2], l[2]); f2bf_pair(pa[r].w, h[3], l[3]);
            *(uint2*)&Ahi[m * A_LDM + kg * 4] = *(uint2*)h;
            *(uint2*)&Alo[m * A_LDM + kg * 4] = *(uint2*)l;
        }
        #pragma unroll
        for (int r = 0; r < 4; r++) {
            const int task = r * 256 + tid;
            const int kr   = task >> 5;
            const int ng   = task & 31;
            __nv_bfloat16 h[4], l[4];
            f2bf_pair(pb[r].x, h[0], l[0]); f2bf_pair(pb[r].y, h[1], l[1]);
            f2bf_pair(pb[r].z, h[2], l[2]); f2bf_pair(pb[r].w, h[3], l[3]);
            *(uint2*)&Bhi[kr * B_LDM + ng * 4] = *(uint2*)h;
            *(uint2*)&Blo[kr * B_LDM + ng * 4] = *(uint2*)l;
        }
    };

    auto compute_stage = [&](int s) {
        const __nv_bfloat16* Ahi = (const __nv_bfloat16*)(sm + s * STAGE_B);
        const __nv_bfloat16* Alo = (const __nv_bfloat16*)(sm + s * STAGE_B + A_PART_B);
        const __nv_bfloat16* Bhi = (const __nv_bfloat16*)(sm + s * STAGE_B + 2 * A_PART_B);
        const __nv_bfloat16* Blo = (const __nv_bfloat16*)(sm + s * STAGE_B + 2 * A_PART_B + B_PART_B);
        #pragma unroll
        for (int kk = 0; kk < KC; kk += 16) {
            wmma::fragment<wmma::matrix_a, 16, 16, 16, __nv_bfloat16, wmma::row_major> ah[2], al[2];
            #pragma unroll
            for (int i = 0; i < 2; i++) {
                const int mrow = wm * 32 + i * 16;
                wmma::load_matrix_sync(ah[i], Ahi + mrow * A_LDM + kk, A_LDM);
                wmma::load_matrix_sync(al[i], Alo + mrow * A_LDM + kk, A_LDM);
            }
            #pragma unroll
            for (int j = 0; j < 4; j++) {
                wmma::fragment<wmma::matrix_b, 16, 16, 16, __nv_bfloat16, wmma::row_major> bh, bl;
                const int ncol = wn * 64 + j * 16;
                wmma::load_matrix_sync(bh, Bhi + kk * B_LDM + ncol, B_LDM);
                wmma::load_matrix_sync(bl, Blo + kk * B_LDM + ncol, B_LDM);
                #pragma unroll
                for (int i = 0; i < 2; i++) {
                    wmma::mma_sync(acc[i][j], ah[i], bh, acc[i][j]);
                    wmma::mma_sync(acc[i][j], ah[i], bl, acc[i][j]);
                    wmma::mma_sync(acc[i][j], al[i], bh, acc[i][j]);
                }
            }
        }
    };

    const int nchunk = Kd / KC;   // 32
    issue_loads(0);
    int s = 0;
    for (int it = 0; it < nchunk; ++it) {
        store_stage(s);
        __syncthreads();
        if (it + 1 < nchunk) issue_loads((it + 1) * KC);   // overlap with MMA
        compute_stage(s);
        __syncthreads();
        s ^= 1;
    }

    // ---- Epilogue: dump accs to smem (f32 128x128), then scatter ----
    float* Cs = (float*)sm;
    #pragma unroll
    for (int i = 0; i < 2; i++)
        #pragma unroll
        for (int j = 0; j < 4; j++)
            wmma::store_matrix_sync(Cs + (wm * 32 + i * 16) * TN + wn * 64 + j * 16,
                                    acc[i][j], TN, wmma::mem_row_major);
    __syncthreads();

    #pragma unroll
    for (int r = 0; r < 16; r++) {
        const int task = r * 256 + tid;      // 0..4095 float4 tasks
        const int m    = task >> 5;          // 0..127
        const int cg   = task & 31;          // float4 col group
        float4 v = *(const float4*)(Cs + m * TN + cg * 4);
        const int row  = row0 + m;
        const int colg = col0 + cg * 4;
        if (MODE == 0) {
            const int t = colg >> 10;
            const int h = (colg >> 6) & (HDIM - 1);
            const int d = colg & (DDIM - 1);
            const int b = row >> 12;
            const int n = row & (NDIM - 1);
            const size_t o = (((size_t)(b * HDIM + h)) * NDIM + n) * DDIM + d;
            if (t == 2) {
                *(float4*)(g_v + o) = v;
            } else {
                v.x = (v.x > 0.f) ? v.x + 1.f : expf(v.x);
                v.y = (v.y > 0.f) ? v.y + 1.f : expf(v.y);
                v.z = (v.z > 0.f) ? v.z + 1.f : expf(v.z);
                v.w = (v.w > 0.f) ? v.w + 1.f : expf(v.w);
                if (t == 0) *(float4*)(g_q + o) = v;
                else        *(float4*)(g_k + o) = v;
            }
        } else {
            v.x += bias[colg];     v.y += bias[colg + 1];
            v.z += bias[colg + 2]; v.w += bias[colg + 3];
            *(float4*)(Cout + (size_t)row * Nd + colg) = v;
        }
    }
}

// ---------------------------------------------------------------------------
// Stage 2a: partial kv[d][e] + ksum[d] over an N-split (validated in R1).
// ---------------------------------------------------------------------------
__global__ __launch_bounds__(256)
void kv_kernel()
{
    const int bh    = blockIdx.x;
    const int split = blockIdx.y;
    const float* Kp = g_k + (size_t)bh * NDIM * DDIM;
    const float* Vp = g_v + (size_t)bh * NDIM * DDIM;

    const int tid = threadIdx.x;
    const int tc = tid & 15, tr = tid >> 4;
    const int d0 = tr * 4, e0 = tc * 4;

    __shared__ float ks[32][64];
    __shared__ float vs[32][64];

    float acc[4][4];
    float ksum[4] = {0.f, 0.f, 0.f, 0.f};
    #pragma unroll
    for (int i = 0; i < 4; i++)
        #pragma unroll
        for (int j = 0; j < 4; j++) acc[i][j] = 0.f;

    const int nBeg = split * (NDIM / NSPLIT);
    const int nEnd = nBeg + (NDIM / NSPLIT);

    for (int nb = nBeg; nb < nEnd; nb += 32) {
        #pragma unroll
        for (int i = 0; i < 2; i++) {
            int idx = tid * 2 + i;
            int r = idx >> 4;
            int c = (idx & 15) * 4;
            *(float4*)&ks[r][c] = *(const float4*)(Kp + (size_t)(nb + r) * DDIM + c);
            *(float4*)&vs[r][c] = *(const float4*)(Vp + (size_t)(nb + r) * DDIM + c);
        }
        __syncthreads();
        #pragma unroll 4
        for (int nn = 0; nn < 32; nn++) {
            float kr[4], vr[4];
            #pragma unroll
            for (int i = 0; i < 4; i++) kr[i] = ks[nn][d0 + i];
            #pragma unroll
            for (int j = 0; j < 4; j++) vr[j] = vs[nn][e0 + j];
            #pragma unroll
            for (int i = 0; i < 4; i++) {
                ksum[i] += kr[i];
                #pragma unroll
                for (int j = 0; j < 4; j++)
                    acc[i][j] = fmaf(kr[i], vr[j], acc[i][j]);
            }
        }
        __syncthreads();
    }

    #pragma unroll
    for (int i = 0; i < 4; i++)
        #pragma unroll
        for (int j = 0; j < 4; j++)
            g_kvp[split][bh][(d0 + i) * DDIM + (e0 + j)] = acc[i][j];
    if (tc == 0)
        #pragma unroll
        for (int i = 0; i < 4; i++)
            g_ksp[split][bh][d0 + i] = ksum[i];
}

// ---------------------------------------------------------------------------
// Stage 2b: out = (q @ kv) / (q . ksum + 1e-6) -> g_attn [B,N,H*D] (validated).
// ---------------------------------------------------------------------------
__global__ __launch_bounds__(256)
void attn_out_kernel()
{
    const int bh   = blockIdx.x;
    const int nblk = blockIdx.y;
    const int b = bh >> 4, h = bh & 15;
    const int tid = threadIdx.x;
    const int tx = tid & 15, ty = tid >> 4;

    __shared__ float kvs[DDIM][DDIM];
    __shared__ float kss[DDIM];
    __shared__ float qs[64][65];

    for (int idx = tid; idx < DDIM * DDIM; idx += 256) {
        float s = 0.f;
        #pragma unroll
        for (int sp = 0; sp < NSPLIT; sp++) s += g_kvp[sp][bh][idx];
        kvs[idx >> 6][idx & 63] = s;
    }
    if (tid < DDIM) {
        float s = 0.f;
        #pragma unroll
        for (int sp = 0; sp < NSPLIT; sp++) s += g_ksp[sp][bh][tid];
        kss[tid] = s;
    }

    const int n0 = nblk * 64;
    const float* Qp = g_q + ((size_t)bh * NDIM + n0) * DDIM;
    #pragma unroll
    for (int i = 0; i < 4; i++) {
        int f = i * 256 + tid;
        int r = f >> 4;
        int c = (f & 15) * 4;
        float4 v = *(const float4*)(Qp + (size_t)r * DDIM + c);
        qs[r][c + 0] = v.x; qs[r][c + 1] = v.y;
        qs[r][c + 2] = v.z; qs[r][c + 3] = v.w;
    }
    __syncthreads();

    float acc[4][4];
    float nrm[4] = {0.f, 0.f, 0.f, 0.f};
    #pragma unroll
    for (int i = 0; i < 4; i++)
        #pragma unroll
        for (int j = 0; j < 4; j++) acc[i][j] = 0.f;

    #pragma unroll 8
    for (int d = 0; d < DDIM; d++) {
        float4 kvr = *(const float4*)&kvs[d][tx * 4];
        float kvj[4] = {kvr.x, kvr.y, kvr.z, kvr.w};
        float ksd = kss[d];
        #pragma unroll
        for (int i = 0; i < 4; i++) {
            float qv = qs[ty * 4 + i][d];
            nrm[i] = fmaf(qv, ksd, nrm[i]);
            #pragma unroll
            for (int j = 0; j < 4; j++)
                acc[i][j] = fmaf(qv, kvj[j], acc[i][j]);
        }
    }

    #pragma unroll
    for (int i = 0; i < 4; i++) {
        int n = n0 + ty * 4 + i;
        float inv = 1.f / (nrm[i] + 1e-6f);
        size_t base = (((size_t)b * NDIM + n) * HDIM + h) * DDIM;
        #pragma unroll
        for (int j = 0; j < 4; j++)
            g_attn[base + tx * 4 + j] = acc[i][j] * inv;
    }
}

// ---------------------------------------------------------------------------
extern "C" void kernel_launch(void* const* d_in, const int* in_sizes, int n_in,
                              void* d_out, int out_size)
{
    const float* x    = (const float*)d_in[0];
    const float* Wqkv = (const float*)d_in[1];
    const float* Wout = (const float*)d_in[2];
    const float* bout = (const float*)d_in[3];
    float* out = (float*)d_out;

    cudaFuncSetAttribute(gemm_wmma<0>, cudaFuncAttributeMaxDynamicSharedMemorySize, DYN_SMEM);
    cudaFuncSetAttribute(gemm_wmma<1>, cudaFuncAttributeMaxDynamicSharedMemorySize, DYN_SMEM);

    // 1) qkv = x @ W_qkv (3xBF16 wmma), fused elu+1 + [B,H,N,D] scatter
    gemm_wmma<0><<<dim3(3 * CDIM / TN, MDIM / TM), 256, DYN_SMEM>>>(
        x, Wqkv, nullptr, nullptr, CDIM, 3 * CDIM);

    // 2a) kv / ksum reduction
    kv_kernel<<<dim3(BDIM * HDIM, NSPLIT), 256>>>();

    // 2b) numerator + normalizer + divide
    attn_out_kernel<<<dim3(BDIM * HDIM, NDIM / 64), 256>>>();

    // 3) out = g_attn @ W_out + b_out (3xBF16 wmma)
    gemm_wmma<1><<<dim3(CDIM / TN, MDIM / TM), 256, DYN_SMEM>>>(
        nullptr, Wout, bout, out, CDIM, CDIM);
}